// round 13
// baseline (speedup 1.0000x reference)
#include <cuda_runtime.h>
#include <cuda_bf16.h>
#include <math.h>
#include <stdint.h>

// ===================== scratch (static; no allocations) =====================
__device__ __nv_bfloat16 g_QKV2m[2048*6144];
__device__ __nv_bfloat16 g_KV2c [1024*4096];
__device__ __nv_bfloat16 g_Q2c  [2048*2048];

__device__ __nv_bfloat16 g_wemb2 [2048*3072];
__device__ __nv_bfloat16 g_pemb2 [1024*3072];
__device__ __nv_bfloat16 g_word2 [2048*3072];
__device__ __nv_bfloat16 g_cross2[2048*3072];
__device__ __nv_bfloat16 g_Wqkvm2[3072*3072];
__device__ __nv_bfloat16 g_Wqc2  [1024*3072];
__device__ __nv_bfloat16 g_Wkvc2 [2048*3072];
__device__ __nv_bfloat16 g_W12   [4096*3072];
__device__ __nv_bfloat16 g_W22   [1024*12288];
__device__ __nv_bfloat16 g_Hf2   [2048*12288];

// ===================== PTX helpers =====================
__device__ __forceinline__ uint32_t smem_u32_of(const void* p) {
    uint32_t a;
    asm("{ .reg .u64 t; cvta.to.shared.u64 t, %1; cvt.u32.u64 %0, t; }" : "=r"(a) : "l"(p));
    return a;
}
#define CP_ASYNC16(sm, gp) \
    asm volatile("cp.async.cg.shared.global [%0], [%1], 16;" :: "r"(sm), "l"(gp))
#define CP_COMMIT() asm volatile("cp.async.commit_group;" ::: "memory")
#define CP_WAIT(n)  asm volatile("cp.async.wait_group %0;" :: "n"(n) : "memory")

__device__ __forceinline__ void ldm_x4(uint32_t& r0, uint32_t& r1, uint32_t& r2, uint32_t& r3,
                                       uint32_t addr) {
    asm volatile("ldmatrix.sync.aligned.m8n8.x4.shared.b16 {%0,%1,%2,%3}, [%4];"
                 : "=r"(r0), "=r"(r1), "=r"(r2), "=r"(r3) : "r"(addr));
}
__device__ __forceinline__ void ldm_x4t(uint32_t& r0, uint32_t& r1, uint32_t& r2, uint32_t& r3,
                                        uint32_t addr) {
    asm volatile("ldmatrix.sync.aligned.m8n8.x4.trans.shared.b16 {%0,%1,%2,%3}, [%4];"
                 : "=r"(r0), "=r"(r1), "=r"(r2), "=r"(r3) : "r"(addr));
}
__device__ __forceinline__ void mma16816(float* c, const uint32_t* a,
                                         uint32_t b0, uint32_t b1) {
    asm volatile("mma.sync.aligned.m16n8k16.row.col.f32.bf16.bf16.f32 "
                 "{%0,%1,%2,%3}, {%4,%5,%6,%7}, {%8,%9}, {%0,%1,%2,%3};"
                 : "+f"(c[0]), "+f"(c[1]), "+f"(c[2]), "+f"(c[3])
                 : "r"(a[0]), "r"(a[1]), "r"(a[2]), "r"(a[3]), "r"(b0), "r"(b1));
}

// ===================== split helpers =====================
__device__ __forceinline__ void split1(float v, unsigned short& h, unsigned short& l) {
    __nv_bfloat16 hb = __float2bfloat16(v);
    __nv_bfloat16 lb = __float2bfloat16(v - __bfloat162float(hb));
    h = __bfloat16_as_ushort(hb);
    l = __bfloat16_as_ushort(lb);
}
__device__ __forceinline__ void pack_hl(float a, float b, uint32_t& hi, uint32_t& lo) {
    unsigned short ha, la, hb, lb;
    split1(a, ha, la);
    split1(b, hb, lb);
    hi = ((uint32_t)hb << 16) | ha;
    lo = ((uint32_t)lb << 16) | la;
}

// ===================== batched split kernel (10 jobs, 1 launch) =============
struct SplitJobs {
    const float*  src[10];
    __nv_bfloat16* dst[10];
    int K[10];
    int mode[10];
    int cum[11];
};

__global__ __launch_bounds__(256)
void split_all(SplitJobs J)
{
    int cid = blockIdx.x * 256 + threadIdx.x;
    if (cid >= J.cum[10]) return;
    int j = 0;
    #pragma unroll
    for (int t = 0; t < 10; t++) if (cid >= J.cum[t + 1]) j = t + 1;
    int local = cid - J.cum[j];
    int K = J.K[j], kq = K >> 2;
    int m = local / kq;
    int k4 = (local - m * kq) << 2;
    float4 v = *(const float4*)(J.src[j] + (size_t)m * K + k4);
    unsigned short h0,h1,h2,h3,l0,l1,l2,l3;
    split1(v.x, h0, l0); split1(v.y, h1, l1);
    split1(v.z, h2, l2); split1(v.w, h3, l3);
    ushort4 H = make_ushort4(h0, h1, h2, h3);
    ushort4 L = make_ushort4(l0, l1, l2, l3);
    unsigned short* D = (unsigned short*)J.dst[j];
    size_t b = (size_t)m * (3 * (size_t)K);
    if (J.mode[j] == 0) {
        *(ushort4*)(D + b + k4)       = H;
        *(ushort4*)(D + b + K + k4)   = L;
        *(ushort4*)(D + b + 2*K + k4) = H;
    } else {
        *(ushort4*)(D + b + k4)       = H;
        *(ushort4*)(D + b + K + k4)   = H;
        *(ushort4*)(D + b + 2*K + k4) = L;
    }
}

// ===================== mma.sync bf16 GEMM — 128x64 tile, 4 warps, 64x32 wtile
struct Bias4 { const float* p[4]; };

#define NSTAGE   4
#define APITCH   80
#define STAGE_A  (128 * APITCH)          // 10240
#define STAGE_B  (64 * APITCH)           // 5120
#define STAGE_AB (STAGE_A + STAGE_B)     // 15360
#define GEMM_SMEM (NSTAGE * STAGE_AB)    // 61440

template<int OUT_MODE>
__global__ __launch_bounds__(128, 3)
void gemm_tc(const __nv_bfloat16* __restrict__ A, const __nv_bfloat16* __restrict__ B,
             Bias4 bias, float* __restrict__ Cf,
             __nv_bfloat16* __restrict__ Cs, int M, int N, int K)
{
    extern __shared__ char smem[];
    const uint32_t sb = smem_u32_of(smem);
    const int tid = threadIdx.x, warp = tid >> 5, lane = tid & 31;
    const int warpM = (warp >> 1) * 64, warpN = (warp & 1) * 32;
    const int bm = blockIdx.y * 128, bn = blockIdx.x * 64;
    const int KT = K >> 5;

    const int lr = tid >> 2, lsg = tid & 3;
    const __nv_bfloat16* Ab = A + (size_t)bm * K;
    const __nv_bfloat16* Bb = B + (size_t)bn * K;

    const int fRow = lane & 15;
    const int fK   = (lane >> 4) * 8;

    float acc[4][4][4];
    #pragma unroll
    for (int i = 0; i < 4; i++)
        #pragma unroll
        for (int j = 0; j < 4; j++)
            #pragma unroll
            for (int q = 0; q < 4; q++) acc[i][j][q] = 0.f;

    #pragma unroll
    for (int s = 0; s < NSTAGE - 1; s++) {
        uint32_t sA = sb + s * STAGE_AB, sB = sA + STAGE_A;
        int kb = s << 5;
        #pragma unroll
        for (int i = 0; i < 4; i++) {
            int row = lr + i * 32;
            CP_ASYNC16(sA + row * APITCH + lsg * 16, Ab + (size_t)row * K + kb + lsg * 8);
        }
        #pragma unroll
        for (int i = 0; i < 2; i++) {
            int row = lr + i * 32;
            CP_ASYNC16(sB + row * APITCH + lsg * 16, Bb + (size_t)row * K + kb + lsg * 8);
        }
        CP_COMMIT();
    }

    for (int t = 0; t < KT; t++) {
        CP_WAIT(NSTAGE - 2);
        __syncthreads();
        const int st = t & (NSTAGE - 1);
        const uint32_t sA = sb + st * STAGE_AB, sB = sA + STAGE_A;

        uint32_t a[4][2][4];
        uint32_t b[2][2][4];
        #pragma unroll
        for (int mt = 0; mt < 4; mt++)
            #pragma unroll
            for (int kt = 0; kt < 2; kt++)
                ldm_x4(a[mt][kt][0], a[mt][kt][1], a[mt][kt][2], a[mt][kt][3],
                       sA + (uint32_t)(warpM + mt * 16 + fRow) * APITCH + (kt * 16 + fK) * 2);
        #pragma unroll
        for (int np = 0; np < 2; np++)
            #pragma unroll
            for (int kt = 0; kt < 2; kt++)
                ldm_x4(b[kt][np][0], b[kt][np][1], b[kt][np][2], b[kt][np][3],
                       sB + (uint32_t)(warpN + np * 16 + fRow) * APITCH + (kt * 16 + fK) * 2);

        #pragma unroll
        for (int mt = 0; mt < 4; mt++)
            #pragma unroll
            for (int np = 0; np < 2; np++)
                #pragma unroll
                for (int kt = 0; kt < 2; kt++) {
                    mma16816(acc[mt][np * 2 + 0], a[mt][kt], b[kt][np][0], b[kt][np][2]);
                    mma16816(acc[mt][np * 2 + 1], a[mt][kt], b[kt][np][1], b[kt][np][3]);
                }

        int tn = t + NSTAGE - 1;
        if (tn < KT) {
            int sn = tn & (NSTAGE - 1);
            uint32_t nA = sb + sn * STAGE_AB, nB = nA + STAGE_A;
            int kb = tn << 5;
            #pragma unroll
            for (int i = 0; i < 4; i++) {
                int row = lr + i * 32;
                CP_ASYNC16(nA + row * APITCH + lsg * 16, Ab + (size_t)row * K + kb + lsg * 8);
            }
            #pragma unroll
            for (int i = 0; i < 2; i++) {
                int row = lr + i * 32;
                CP_ASYNC16(nB + row * APITCH + lsg * 16, Bb + (size_t)row * K + kb + lsg * 8);
            }
        }
        CP_COMMIT();
    }

    #pragma unroll
    for (int mt = 0; mt < 4; mt++) {
        int rg = bm + warpM + mt * 16 + (lane >> 2);
        #pragma unroll
        for (int nt = 0; nt < 4; nt++) {
            int gcol = bn + warpN + nt * 8 + (lane & 3) * 2;
            float bx = __ldg(&bias.p[gcol >> 10][gcol & 1023]);
            float by = __ldg(&bias.p[(gcol + 1) >> 10][(gcol + 1) & 1023]);
            float* ac = acc[mt][nt];
            if (OUT_MODE == 0) {
                float2 v0 = make_float2(ac[0] + bx, ac[1] + by);
                float2 v1 = make_float2(ac[2] + bx, ac[3] + by);
                *(float2*)&Cf[(size_t)rg * N + gcol]       = v0;
                *(float2*)&Cf[(size_t)(rg + 8) * N + gcol] = v1;
            } else if (OUT_MODE == 1) {
                float v0 = fmaxf(ac[0] + bx, 0.f), v1 = fmaxf(ac[1] + by, 0.f);
                float v2 = fmaxf(ac[2] + bx, 0.f), v3 = fmaxf(ac[3] + by, 0.f);
                unsigned short h0,h1,h2,h3,l0,l1,l2,l3;
                split1(v0, h0, l0); split1(v1, h1, l1);
                split1(v2, h2, l2); split1(v3, h3, l3);
                unsigned short* D = (unsigned short*)Cs;
                size_t b0r = (size_t)rg * (3 * (size_t)N);
                size_t b1r = (size_t)(rg + 8) * (3 * (size_t)N);
                *(ushort2*)(D + b0r + gcol)       = make_ushort2(h0, h1);
                *(ushort2*)(D + b0r + N + gcol)   = make_ushort2(l0, l1);
                *(ushort2*)(D + b0r + 2*N + gcol) = make_ushort2(h0, h1);
                *(ushort2*)(D + b1r + gcol)       = make_ushort2(h2, h3);
                *(ushort2*)(D + b1r + N + gcol)   = make_ushort2(l2, l3);
                *(ushort2*)(D + b1r + 2*N + gcol) = make_ushort2(h2, h3);
            } else {
                float v0 = ac[0] + bx, v1 = ac[1] + by;
                float v2 = ac[2] + bx, v3 = ac[3] + by;
                unsigned short h0,h1,h2,h3,l0,l1,l2,l3;
                split1(v0, h0, l0); split1(v1, h1, l1);
                split1(v2, h2, l2); split1(v3, h3, l3);
                unsigned short* D = (unsigned short*)Cs;
                size_t b0r = (size_t)rg * (2 * (size_t)N);
                size_t b1r = (size_t)(rg + 8) * (2 * (size_t)N);
                *(ushort2*)(D + b0r + gcol)     = make_ushort2(h0, h1);
                *(ushort2*)(D + b0r + N + gcol) = make_ushort2(l0, l1);
                *(ushort2*)(D + b1r + gcol)     = make_ushort2(h2, h3);
                *(ushort2*)(D + b1r + N + gcol) = make_ushort2(l2, l3);
            }
        }
    }
}

// ===================== tensor-core flash attention (strided inputs) =========
#define APIT 72
#define APLANE (64 * APIT)
#define ASTAGE (4 * APLANE)
#define ATTN_SMEM (2 * ASTAGE * 2)

template<int CAUSAL>
__global__ __launch_bounds__(128)
void attn_tc(const __nv_bfloat16* __restrict__ Qb, const __nv_bfloat16* __restrict__ Kb,
             const __nv_bfloat16* __restrict__ Vb, __nv_bfloat16* __restrict__ O2,
             int Sk, int qstride, int qlooff, int kvstride, int kvlooff)
{
    extern __shared__ __nv_bfloat16 smb[];
    const uint32_t uS0 = smem_u32_of(smb);
    const uint32_t uS1 = uS0 + ASTAGE * 2;

    const int h = blockIdx.y;
    const int bx = CAUSAL ? ((int)gridDim.x - 1 - (int)blockIdx.x) : (int)blockIdx.x;
    const int r0 = bx * 64;
    const int tid = threadIdx.x, w = tid >> 5, lane = tid & 31;
    const int fr = lane & 15, fo = (lane >> 4) * 8;
    const int headoff = h * 64;

    #pragma unroll
    for (int i = 0; i < 8; i++) {
        int cid = i * 128 + tid;
        int plane = cid >> 9, row = (cid >> 3) & 63, seg = cid & 7;
        uint32_t dst = uS1 + (uint32_t)(plane * APLANE + row * APIT + seg * 8) * 2;
        const __nv_bfloat16* src = Qb + (size_t)(r0 + row) * qstride + plane * qlooff + headoff + seg * 8;
        CP_ASYNC16(dst, src);
    }
    CP_COMMIT();
    #pragma unroll
    for (int i = 0; i < 16; i++) {
        int cid = i * 128 + tid;
        int plane = cid >> 9, row = (cid >> 3) & 63, seg = cid & 7;
        uint32_t dst = uS0 + (uint32_t)(plane * APLANE + row * APIT + seg * 8) * 2;
        const __nv_bfloat16* base = (plane < 2) ? Kb : Vb;
        const __nv_bfloat16* src = base + (size_t)row * kvstride + (plane & 1) * kvlooff + headoff + seg * 8;
        CP_ASYNC16(dst, src);
    }
    CP_COMMIT();

    CP_WAIT(1);
    __syncthreads();
    uint32_t qh[4][4], ql[4][4];
    #pragma unroll
    for (int kt = 0; kt < 4; kt++) {
        uint32_t off = (uint32_t)(w * 16 + fr) * (APIT * 2) + (kt * 16 + fo) * 2;
        ldm_x4(qh[kt][0], qh[kt][1], qh[kt][2], qh[kt][3], uS0 + ASTAGE * 2 + off);
        ldm_x4(ql[kt][0], ql[kt][1], ql[kt][2], ql[kt][3], uS0 + ASTAGE * 2 + APLANE * 2 + off);
    }
    __syncthreads();

    float o[8][4];
    #pragma unroll
    for (int n = 0; n < 8; n++)
        #pragma unroll
        for (int q = 0; q < 4; q++) o[n][q] = 0.f;
    float m0 = -1e30f, m1 = -1e30f, l0 = 0.f, l1 = 0.f;

    const int nt = CAUSAL ? (bx + 1) : (Sk >> 6);
    for (int t = 0; t < nt; t++) {
        if (t + 1 < nt) {
            const int c1 = (t + 1) * 64;
            const uint32_t uSn = ((t + 1) & 1) ? uS1 : uS0;
            #pragma unroll
            for (int i = 0; i < 16; i++) {
                int cid = i * 128 + tid;
                int plane = cid >> 9, row = (cid >> 3) & 63, seg = cid & 7;
                uint32_t dst = uSn + (uint32_t)(plane * APLANE + row * APIT + seg * 8) * 2;
                const __nv_bfloat16* base = (plane < 2) ? Kb : Vb;
                const __nv_bfloat16* src = base + (size_t)(c1 + row) * kvstride + (plane & 1) * kvlooff + headoff + seg * 8;
                CP_ASYNC16(dst, src);
            }
        }
        CP_COMMIT();
        CP_WAIT(1);
        __syncthreads();

        const uint32_t uKhi = ((t & 1) ? uS1 : uS0);
        const uint32_t uKlo = uKhi + APLANE * 2;
        const uint32_t uVhi = uKhi + 2 * APLANE * 2;
        const uint32_t uVlo = uKhi + 3 * APLANE * 2;
        const int c0 = t * 64;

        float s[8][4];
        #pragma unroll
        for (int n = 0; n < 8; n++)
            #pragma unroll
            for (int q = 0; q < 4; q++) s[n][q] = 0.f;
        #pragma unroll
        for (int np = 0; np < 4; np++) {
            uint32_t bh[4][4], bl[4][4];
            #pragma unroll
            for (int kt = 0; kt < 4; kt++) {
                uint32_t off = (uint32_t)(np * 16 + fr) * (APIT * 2) + (kt * 16 + fo) * 2;
                ldm_x4(bh[kt][0], bh[kt][1], bh[kt][2], bh[kt][3], uKhi + off);
                ldm_x4(bl[kt][0], bl[kt][1], bl[kt][2], bl[kt][3], uKlo + off);
            }
            #pragma unroll
            for (int kt = 0; kt < 4; kt++) {
                mma16816(s[np*2+0], qh[kt], bh[kt][0], bh[kt][2]);
                mma16816(s[np*2+1], qh[kt], bh[kt][1], bh[kt][3]);
                mma16816(s[np*2+0], ql[kt], bh[kt][0], bh[kt][2]);
                mma16816(s[np*2+1], ql[kt], bh[kt][1], bh[kt][3]);
                mma16816(s[np*2+0], qh[kt], bl[kt][0], bl[kt][2]);
                mma16816(s[np*2+1], qh[kt], bl[kt][1], bl[kt][3]);
            }
        }
        #pragma unroll
        for (int n = 0; n < 8; n++) {
            s[n][0] *= 0.125f; s[n][1] *= 0.125f;
            s[n][2] *= 0.125f; s[n][3] *= 0.125f;
        }

        if (CAUSAL && t == nt - 1) {
            int gr0 = r0 + w * 16 + (lane >> 2);
            int gr1 = gr0 + 8;
            #pragma unroll
            for (int n = 0; n < 8; n++) {
                int col = c0 + n * 8 + (lane & 3) * 2;
                if (col     > gr0) s[n][0] = -1e30f;
                if (col + 1 > gr0) s[n][1] = -1e30f;
                if (col     > gr1) s[n][2] = -1e30f;
                if (col + 1 > gr1) s[n][3] = -1e30f;
            }
        }

        float mx0 = -1e30f, mx1 = -1e30f;
        #pragma unroll
        for (int n = 0; n < 8; n++) {
            mx0 = fmaxf(mx0, fmaxf(s[n][0], s[n][1]));
            mx1 = fmaxf(mx1, fmaxf(s[n][2], s[n][3]));
        }
        mx0 = fmaxf(mx0, __shfl_xor_sync(0xffffffffu, mx0, 1));
        mx0 = fmaxf(mx0, __shfl_xor_sync(0xffffffffu, mx0, 2));
        mx1 = fmaxf(mx1, __shfl_xor_sync(0xffffffffu, mx1, 1));
        mx1 = fmaxf(mx1, __shfl_xor_sync(0xffffffffu, mx1, 2));
        float mn0 = fmaxf(m0, mx0), mn1 = fmaxf(m1, mx1);
        float cor0 = __expf(m0 - mn0), cor1 = __expf(m1 - mn1);
        m0 = mn0; m1 = mn1;
        float ps0 = 0.f, ps1 = 0.f;
        #pragma unroll
        for (int n = 0; n < 8; n++) {
            s[n][0] = __expf(s[n][0] - mn0);
            s[n][1] = __expf(s[n][1] - mn0);
            s[n][2] = __expf(s[n][2] - mn1);
            s[n][3] = __expf(s[n][3] - mn1);
            ps0 += s[n][0] + s[n][1];
            ps1 += s[n][2] + s[n][3];
        }
        ps0 += __shfl_xor_sync(0xffffffffu, ps0, 1);
        ps0 += __shfl_xor_sync(0xffffffffu, ps0, 2);
        ps1 += __shfl_xor_sync(0xffffffffu, ps1, 1);
        ps1 += __shfl_xor_sync(0xffffffffu, ps1, 2);
        l0 = l0 * cor0 + ps0;
        l1 = l1 * cor1 + ps1;
        #pragma unroll
        for (int n = 0; n < 8; n++) {
            o[n][0] *= cor0; o[n][1] *= cor0;
            o[n][2] *= cor1; o[n][3] *= cor1;
        }

        uint32_t ph[4][4], pl[4][4];
        #pragma unroll
        for (int kt = 0; kt < 4; kt++) {
            int n0 = 2 * kt, n1 = n0 + 1;
            pack_hl(s[n0][0], s[n0][1], ph[kt][0], pl[kt][0]);
            pack_hl(s[n0][2], s[n0][3], ph[kt][1], pl[kt][1]);
            pack_hl(s[n1][0], s[n1][1], ph[kt][2], pl[kt][2]);
            pack_hl(s[n1][2], s[n1][3], ph[kt][3], pl[kt][3]);
        }

        #pragma unroll
        for (int dp = 0; dp < 4; dp++) {
            uint32_t vh[4][4], vl[4][4];
            #pragma unroll
            for (int kj = 0; kj < 4; kj++) {
                uint32_t off = (uint32_t)(kj * 16 + fr) * (APIT * 2) + (dp * 16 + fo) * 2;
                ldm_x4t(vh[kj][0], vh[kj][1], vh[kj][2], vh[kj][3], uVhi + off);
                ldm_x4t(vl[kj][0], vl[kj][1], vl[kj][2], vl[kj][3], uVlo + off);
            }
            #pragma unroll
            for (int kj = 0; kj < 4; kj++) {
                mma16816(o[dp*2+0], ph[kj], vh[kj][0], vh[kj][1]);
                mma16816(o[dp*2+1], ph[kj], vh[kj][2], vh[kj][3]);
                mma16816(o[dp*2+0], pl[kj], vh[kj][0], vh[kj][1]);
                mma16816(o[dp*2+1], pl[kj], vh[kj][2], vh[kj][3]);
                mma16816(o[dp*2+0], ph[kj], vl[kj][0], vl[kj][1]);
                mma16816(o[dp*2+1], ph[kj], vl[kj][2], vl[kj][3]);
            }
        }
        __syncthreads();
    }

    float inv0 = 1.f / l0, inv1 = 1.f / l1;
    int gr0 = r0 + w * 16 + (lane >> 2);
    unsigned short* D = (unsigned short*)O2;
    #pragma unroll
    for (int n = 0; n < 8; n++) {
        int col = h * 64 + n * 8 + (lane & 3) * 2;
        float v0 = o[n][0] * inv0, v1 = o[n][1] * inv0;
        float v2 = o[n][2] * inv1, v3 = o[n][3] * inv1;
        unsigned short h0,h1,h2,h3,l0s,l1s,l2s,l3s;
        split1(v0, h0, l0s); split1(v1, h1, l1s);
        split1(v2, h2, l2s); split1(v3, h3, l3s);
        size_t b0r = (size_t)gr0 * 3072;
        size_t b1r = (size_t)(gr0 + 8) * 3072;
        *(ushort2*)(D + b0r + col)        = make_ushort2(h0, h1);
        *(ushort2*)(D + b0r + 1024 + col) = make_ushort2(l0s, l1s);
        *(ushort2*)(D + b0r + 2048 + col) = make_ushort2(h0, h1);
        *(ushort2*)(D + b1r + col)        = make_ushort2(h2, h3);
        *(ushort2*)(D + b1r + 1024 + col) = make_ushort2(l2s, l3s);
        *(ushort2*)(D + b1r + 2048 + col) = make_ushort2(h2, h3);
    }
}

// ===================== launch =====================
extern "C" void kernel_launch(void* const* d_in, const int* in_sizes, int n_in,
                              void* d_out, int out_size)
{
    const float* wemb = (const float*)d_in[0];
    const float* pemb = (const float*)d_in[1];
    const float* Wq_m = (const float*)d_in[2];
    const float* bq_m = (const float*)d_in[3];
    const float* Wk_m = (const float*)d_in[4];
    const float* bk_m = (const float*)d_in[5];
    const float* Wv_m = (const float*)d_in[6];
    const float* bv_m = (const float*)d_in[7];
    const float* Wq_c = (const float*)d_in[8];
    const float* bq_c = (const float*)d_in[9];
    const float* Wk_c = (const float*)d_in[10];
    const float* bk_c = (const float*)d_in[11];
    const float* Wv_c = (const float*)d_in[12];
    const float* bv_c = (const float*)d_in[13];
    const float* W1   = (const float*)d_in[14];
    const float* b1   = (const float*)d_in[15];
    const float* W2   = (const float*)d_in[16];
    const float* b2   = (const float*)d_in[17];
    float* out = (float*)d_out;

    __nv_bfloat16 *QKV2m, *KV2c, *Q2c;
    __nv_bfloat16 *wemb2, *pemb2, *word2, *cross2;
    __nv_bfloat16 *Wqkvm2, *Wqc2, *Wkvc2, *W12, *W22, *Hf2;
    cudaGetSymbolAddress((void**)&QKV2m, g_QKV2m);
    cudaGetSymbolAddress((void**)&KV2c, g_KV2c);
    cudaGetSymbolAddress((void**)&Q2c, g_Q2c);
    cudaGetSymbolAddress((void**)&wemb2, g_wemb2);
    cudaGetSymbolAddress((void**)&pemb2, g_pemb2);
    cudaGetSymbolAddress((void**)&word2, g_word2);
    cudaGetSymbolAddress((void**)&cross2, g_cross2);
    cudaGetSymbolAddress((void**)&Wqkvm2, g_Wqkvm2);
    cudaGetSymbolAddress((void**)&Wqc2, g_Wqc2);
    cudaGetSymbolAddress((void**)&Wkvc2, g_Wkvc2);
    cudaGetSymbolAddress((void**)&W12, g_W12);
    cudaGetSymbolAddress((void**)&W22, g_W22);
    cudaGetSymbolAddress((void**)&Hf2, g_Hf2);

    cudaFuncSetAttribute((const void*)gemm_tc<0>,
                         cudaFuncAttributeMaxDynamicSharedMemorySize, GEMM_SMEM);
    cudaFuncSetAttribute((const void*)gemm_tc<1>,
                         cudaFuncAttributeMaxDynamicSharedMemorySize, GEMM_SMEM);
    cudaFuncSetAttribute((const void*)gemm_tc<2>,
                         cudaFuncAttributeMaxDynamicSharedMemorySize, GEMM_SMEM);
    cudaFuncSetAttribute((const void*)attn_tc<0>,
                         cudaFuncAttributeMaxDynamicSharedMemorySize, ATTN_SMEM);
    cudaFuncSetAttribute((const void*)attn_tc<1>,
                         cudaFuncAttributeMaxDynamicSharedMemorySize, ATTN_SMEM);

    // ---- single batched split launch (weights concatenated for fused GEMMs)
    SplitJobs J;
    const float* srcs[10]  = {wemb, pemb, Wq_m, Wk_m, Wv_m, Wq_c, Wk_c, Wv_c, W1, W2};
    __nv_bfloat16* dsts[10] = {wemb2, pemb2,
                               Wqkvm2, Wqkvm2 + (size_t)1024*3072, Wqkvm2 + (size_t)2048*3072,
                               Wqc2,
                               Wkvc2, Wkvc2 + (size_t)1024*3072,
                               W12, W22};
    int Ms[10]   = {2048, 1024, 1024, 1024, 1024, 1024, 1024, 1024, 4096, 1024};
    int Ks[10]   = {1024, 1024, 1024, 1024, 1024, 1024, 1024, 1024, 1024, 4096};
    int modes[10] = {0, 0, 1, 1, 1, 1, 1, 1, 1, 1};
    int cum = 0;
    for (int j = 0; j < 10; j++) {
        J.src[j] = srcs[j]; J.dst[j] = dsts[j];
        J.K[j] = Ks[j]; J.mode[j] = modes[j];
        J.cum[j] = cum;
        cum += Ms[j] * (Ks[j] >> 2);
    }
    J.cum[10] = cum;
    split_all<<<(cum + 255) / 256, 256>>>(J);                                           // 1

    Bias4 Bqkv  = {{bq_m, bk_m, bv_m, bq_m}};
    Bias4 Bkvc  = {{bk_c, bv_c, bk_c, bv_c}};
    Bias4 Bqc   = {{bq_c, bq_c, bq_c, bq_c}};
    Bias4 Bf1   = {{b1, b1 + 1024, b1 + 2048, b1 + 3072}};
    Bias4 Bf2   = {{b2, b2, b2, b2}};

    gemm_tc<2><<<dim3(48, 16), 128, GEMM_SMEM>>>(wemb2, Wqkvm2, Bqkv, nullptr, QKV2m, 2048, 3072, 3072); // 2
    gemm_tc<2><<<dim3(32, 8),  128, GEMM_SMEM>>>(pemb2, Wkvc2, Bkvc, nullptr, KV2c, 1024, 2048, 3072);   // 3
    attn_tc<1><<<dim3(32, 16), 128, ATTN_SMEM>>>(QKV2m, QKV2m + 1024, QKV2m + 2048, word2,
                                                 2048, 6144, 3072, 6144, 3072);                          // 4
    gemm_tc<2><<<dim3(16, 16), 128, GEMM_SMEM>>>(word2, Wqc2, Bqc, nullptr, Q2c, 2048, 1024, 3072);      // 5
    attn_tc<0><<<dim3(32, 16), 128, ATTN_SMEM>>>(Q2c, KV2c, KV2c + 1024, cross2,
                                                 1024, 2048, 1024, 4096, 2048);                          // 6
    gemm_tc<1><<<dim3(64, 16), 128, GEMM_SMEM>>>(cross2, W12, Bf1, nullptr, Hf2, 2048, 4096, 3072);      // 7
    gemm_tc<0><<<dim3(16, 16), 128, GEMM_SMEM>>>(Hf2, W22, Bf2, out, nullptr, 2048, 1024, 12288);        // 8
}

// round 14
// speedup vs baseline: 1.1221x; 1.1221x over previous
#include <cuda_runtime.h>
#include <cuda_bf16.h>
#include <math.h>
#include <stdint.h>

// ===================== scratch (static; no allocations) =====================
// planar 2-plane (for attention consumption): row = [hi(N) | lo(N)], stride 2N
__device__ __nv_bfloat16 g_QKV2m[2048*6144];
__device__ __nv_bfloat16 g_KV2c [1024*4096];
__device__ __nv_bfloat16 g_Q2c  [2048*2048];

// interleaved 2-plane ("i2", GEMM operands): per 32-K chunk [hi32|lo32], row len 2K
__device__ __nv_bfloat16 g_wemb2 [2048*2048];
__device__ __nv_bfloat16 g_pemb2 [1024*2048];
__device__ __nv_bfloat16 g_word2 [2048*2048];
__device__ __nv_bfloat16 g_cross2[2048*2048];
__device__ __nv_bfloat16 g_Wqkvm2[3072*2048];
__device__ __nv_bfloat16 g_Wqc2  [1024*2048];
__device__ __nv_bfloat16 g_Wkvc2 [2048*2048];
__device__ __nv_bfloat16 g_W12   [4096*2048];
__device__ __nv_bfloat16 g_W22   [1024*8192];
__device__ __nv_bfloat16 g_Hf2   [2048*8192];

// ===================== PTX helpers =====================
__device__ __forceinline__ uint32_t smem_u32_of(const void* p) {
    uint32_t a;
    asm("{ .reg .u64 t; cvta.to.shared.u64 t, %1; cvt.u32.u64 %0, t; }" : "=r"(a) : "l"(p));
    return a;
}
#define CP_ASYNC16(sm, gp) \
    asm volatile("cp.async.cg.shared.global [%0], [%1], 16;" :: "r"(sm), "l"(gp))
#define CP_COMMIT() asm volatile("cp.async.commit_group;" ::: "memory")
#define CP_WAIT(n)  asm volatile("cp.async.wait_group %0;" :: "n"(n) : "memory")

__device__ __forceinline__ void ldm_x4(uint32_t& r0, uint32_t& r1, uint32_t& r2, uint32_t& r3,
                                       uint32_t addr) {
    asm volatile("ldmatrix.sync.aligned.m8n8.x4.shared.b16 {%0,%1,%2,%3}, [%4];"
                 : "=r"(r0), "=r"(r1), "=r"(r2), "=r"(r3) : "r"(addr));
}
__device__ __forceinline__ void ldm_x4t(uint32_t& r0, uint32_t& r1, uint32_t& r2, uint32_t& r3,
                                        uint32_t addr) {
    asm volatile("ldmatrix.sync.aligned.m8n8.x4.trans.shared.b16 {%0,%1,%2,%3}, [%4];"
                 : "=r"(r0), "=r"(r1), "=r"(r2), "=r"(r3) : "r"(addr));
}
__device__ __forceinline__ void mma16816(float* c, const uint32_t* a,
                                         uint32_t b0, uint32_t b1) {
    asm volatile("mma.sync.aligned.m16n8k16.row.col.f32.bf16.bf16.f32 "
                 "{%0,%1,%2,%3}, {%4,%5,%6,%7}, {%8,%9}, {%0,%1,%2,%3};"
                 : "+f"(c[0]), "+f"(c[1]), "+f"(c[2]), "+f"(c[3])
                 : "r"(a[0]), "r"(a[1]), "r"(a[2]), "r"(a[3]), "r"(b0), "r"(b1));
}

// ===================== split helpers =====================
__device__ __forceinline__ void split1(float v, unsigned short& h, unsigned short& l) {
    __nv_bfloat16 hb = __float2bfloat16(v);
    __nv_bfloat16 lb = __float2bfloat16(v - __bfloat162float(hb));
    h = __bfloat16_as_ushort(hb);
    l = __bfloat16_as_ushort(lb);
}
__device__ __forceinline__ void pack_hl(float a, float b, uint32_t& hi, uint32_t& lo) {
    unsigned short ha, la, hb, lb;
    split1(a, ha, la);
    split1(b, hb, lb);
    hi = ((uint32_t)hb << 16) | ha;
    lo = ((uint32_t)lb << 16) | la;
}

// ===================== batched split kernel (i2 output, 1 launch) ===========
struct SplitJobs {
    const float*  src[10];
    __nv_bfloat16* dst[10];
    int K[10];
    int cum[11];
};

__global__ __launch_bounds__(256)
void split_all(SplitJobs J)
{
    int cid = blockIdx.x * 256 + threadIdx.x;
    if (cid >= J.cum[10]) return;
    int j = 0;
    #pragma unroll
    for (int t = 0; t < 10; t++) if (cid >= J.cum[t + 1]) j = t + 1;
    int local = cid - J.cum[j];
    int K = J.K[j], kq = K >> 2;
    int m = local / kq;
    int k4 = (local - m * kq) << 2;
    float4 v = *(const float4*)(J.src[j] + (size_t)m * K + k4);
    unsigned short h0,h1,h2,h3,l0,l1,l2,l3;
    split1(v.x, h0, l0); split1(v.y, h1, l1);
    split1(v.z, h2, l2); split1(v.w, h3, l3);
    unsigned short* D = (unsigned short*)J.dst[j];
    size_t base = (size_t)m * (2 * (size_t)K) + ((k4 >> 5) << 6) + (k4 & 31);
    *(ushort4*)(D + base)      = make_ushort4(h0, h1, h2, h3);
    *(ushort4*)(D + base + 32) = make_ushort4(l0, l1, l2, l3);
}

// ===================== i2 GEMM — 128x128, 512 thr, reg-reuse 3-term =========
// Per 32-K iter: 16 ldmatrix : 48 MMA (vs 24:48 in triple-K formulation).
struct Bias4 { const float* p[4]; };

#define NSTAGE   4
#define GPITCH   144                     // 64 ext bf16 = 128B + 16B pad
#define GSTAGE_A (128 * GPITCH)          // 18432
#define GSTAGE   (2 * GSTAGE_A)          // 36864
#define GEMM_SMEM (NSTAGE * GSTAGE)      // 147456

template<int OUT_MODE>
__global__ __launch_bounds__(512, 1)
void gemm_tc(const __nv_bfloat16* __restrict__ A2, const __nv_bfloat16* __restrict__ B2,
             Bias4 bias, float* __restrict__ Cf,
             __nv_bfloat16* __restrict__ Cs, int M, int N, int K)
{
    extern __shared__ char smem[];
    const uint32_t sb = smem_u32_of(smem);
    const int tid = threadIdx.x, warp = tid >> 5, lane = tid & 31;
    const int warpM = (warp >> 2) * 32, warpN = (warp & 3) * 32;
    const int bm = blockIdx.y * 128, bn = blockIdx.x * 128;
    const int KT = K >> 5;
    const size_t K2 = 2 * (size_t)K;

    const int lr = tid >> 2, ls = tid & 3;
    const __nv_bfloat16* Ab = A2 + (size_t)bm * K2;
    const __nv_bfloat16* Bb = B2 + (size_t)bn * K2;

    const int fRow = lane & 15;
    const int fK   = (lane >> 4) * 8;

    float acc[2][4][4];
    #pragma unroll
    for (int i = 0; i < 2; i++)
        #pragma unroll
        for (int j = 0; j < 4; j++)
            #pragma unroll
            for (int q = 0; q < 4; q++) acc[i][j][q] = 0.f;

    #pragma unroll
    for (int s = 0; s < NSTAGE - 1; s++) {
        uint32_t sA = sb + s * GSTAGE, sBt = sA + GSTAGE_A;
        int e0 = s << 6;
        CP_ASYNC16(sA  + lr * GPITCH + ls * 16,      Ab + (size_t)lr * K2 + e0 + ls * 8);
        CP_ASYNC16(sA  + lr * GPITCH + ls * 16 + 64, Ab + (size_t)lr * K2 + e0 + ls * 8 + 32);
        CP_ASYNC16(sBt + lr * GPITCH + ls * 16,      Bb + (size_t)lr * K2 + e0 + ls * 8);
        CP_ASYNC16(sBt + lr * GPITCH + ls * 16 + 64, Bb + (size_t)lr * K2 + e0 + ls * 8 + 32);
        CP_COMMIT();
    }

    for (int t = 0; t < KT; t++) {
        CP_WAIT(NSTAGE - 2);
        __syncthreads();
        const int st = t & (NSTAGE - 1);
        const uint32_t sA = sb + st * GSTAGE, sBt = sA + GSTAGE_A;

        // A fragments: [mt][plane][kt] — loaded once, reused for 2 product terms
        uint32_t a[2][2][2][4];
        #pragma unroll
        for (int mt = 0; mt < 2; mt++)
            #pragma unroll
            for (int p = 0; p < 2; p++)
                #pragma unroll
                for (int kt = 0; kt < 2; kt++)
                    ldm_x4(a[mt][p][kt][0], a[mt][p][kt][1], a[mt][p][kt][2], a[mt][p][kt][3],
                           sA + (uint32_t)(warpM + mt * 16 + fRow) * GPITCH
                              + (p * 32 + kt * 16 + fK) * 2);

        #pragma unroll
        for (int nt = 0; nt < 2; nt++) {
            uint32_t bh[2][4], bl[2][4];
            #pragma unroll
            for (int kt = 0; kt < 2; kt++) {
                uint32_t bo = sBt + (uint32_t)(warpN + nt * 16 + fRow) * GPITCH;
                ldm_x4(bh[kt][0], bh[kt][1], bh[kt][2], bh[kt][3], bo + (kt * 16 + fK) * 2);
                ldm_x4(bl[kt][0], bl[kt][1], bl[kt][2], bl[kt][3], bo + (32 + kt * 16 + fK) * 2);
            }
            #pragma unroll
            for (int mt = 0; mt < 2; mt++)
                #pragma unroll
                for (int kt = 0; kt < 2; kt++) {
                    float* c0 = acc[mt][nt * 2 + 0];
                    float* c1 = acc[mt][nt * 2 + 1];
                    mma16816(c0, a[mt][0][kt], bh[kt][0], bh[kt][2]);   // hi*hi
                    mma16816(c1, a[mt][0][kt], bh[kt][1], bh[kt][3]);
                    mma16816(c0, a[mt][1][kt], bh[kt][0], bh[kt][2]);   // lo*hi
                    mma16816(c1, a[mt][1][kt], bh[kt][1], bh[kt][3]);
                    mma16816(c0, a[mt][0][kt], bl[kt][0], bl[kt][2]);   // hi*lo
                    mma16816(c1, a[mt][0][kt], bl[kt][1], bl[kt][3]);
                }
        }

        int tn = t + NSTAGE - 1;
        if (tn < KT) {
            int sn = tn & (NSTAGE - 1);
            uint32_t nA = sb + sn * GSTAGE, nB = nA + GSTAGE_A;
            int e0 = tn << 6;
            CP_ASYNC16(nA + lr * GPITCH + ls * 16,      Ab + (size_t)lr * K2 + e0 + ls * 8);
            CP_ASYNC16(nA + lr * GPITCH + ls * 16 + 64, Ab + (size_t)lr * K2 + e0 + ls * 8 + 32);
            CP_ASYNC16(nB + lr * GPITCH + ls * 16,      Bb + (size_t)lr * K2 + e0 + ls * 8);
            CP_ASYNC16(nB + lr * GPITCH + ls * 16 + 64, Bb + (size_t)lr * K2 + e0 + ls * 8 + 32);
        }
        CP_COMMIT();
    }

    #pragma unroll
    for (int mt = 0; mt < 2; mt++) {
        int rg = bm + warpM + mt * 16 + (lane >> 2);
        #pragma unroll
        for (int nt = 0; nt < 4; nt++) {
            int gcol = bn + warpN + nt * 8 + (lane & 3) * 2;
            float bx = __ldg(&bias.p[gcol >> 10][gcol & 1023]);
            float by = __ldg(&bias.p[(gcol + 1) >> 10][(gcol + 1) & 1023]);
            float* ac = acc[mt][nt];
            if (OUT_MODE == 0) {
                float2 v0 = make_float2(ac[0] + bx, ac[1] + by);
                float2 v1 = make_float2(ac[2] + bx, ac[3] + by);
                *(float2*)&Cf[(size_t)rg * N + gcol]       = v0;
                *(float2*)&Cf[(size_t)(rg + 8) * N + gcol] = v1;
            } else if (OUT_MODE == 1) {
                // relu + i2 (ext row stride 2N)
                float v0 = fmaxf(ac[0] + bx, 0.f), v1 = fmaxf(ac[1] + by, 0.f);
                float v2 = fmaxf(ac[2] + bx, 0.f), v3 = fmaxf(ac[3] + by, 0.f);
                unsigned short h0,h1,h2,h3,l0,l1,l2,l3;
                split1(v0, h0, l0); split1(v1, h1, l1);
                split1(v2, h2, l2); split1(v3, h3, l3);
                unsigned short* D = (unsigned short*)Cs;
                uint32_t coff = ((uint32_t)(gcol >> 5) << 6) + (gcol & 31);
                size_t b0r = (size_t)rg * (2 * (size_t)N) + coff;
                size_t b1r = (size_t)(rg + 8) * (2 * (size_t)N) + coff;
                *(ushort2*)(D + b0r)      = make_ushort2(h0, h1);
                *(ushort2*)(D + b0r + 32) = make_ushort2(l0, l1);
                *(ushort2*)(D + b1r)      = make_ushort2(h2, h3);
                *(ushort2*)(D + b1r + 32) = make_ushort2(l2, l3);
            } else {
                // planar 2-plane (attention input), row stride 2N
                float v0 = ac[0] + bx, v1 = ac[1] + by;
                float v2 = ac[2] + bx, v3 = ac[3] + by;
                unsigned short h0,h1,h2,h3,l0,l1,l2,l3;
                split1(v0, h0, l0); split1(v1, h1, l1);
                split1(v2, h2, l2); split1(v3, h3, l3);
                unsigned short* D = (unsigned short*)Cs;
                size_t b0r = (size_t)rg * (2 * (size_t)N);
                size_t b1r = (size_t)(rg + 8) * (2 * (size_t)N);
                *(ushort2*)(D + b0r + gcol)     = make_ushort2(h0, h1);
                *(ushort2*)(D + b0r + N + gcol) = make_ushort2(l0, l1);
                *(ushort2*)(D + b1r + gcol)     = make_ushort2(h2, h3);
                *(ushort2*)(D + b1r + N + gcol) = make_ushort2(l2, l3);
            }
        }
    }
}

// ===================== tensor-core flash attention (planar in, i2 out) ======
#define APIT 72
#define APLANE (64 * APIT)
#define ASTAGE (4 * APLANE)
#define ATTN_SMEM (2 * ASTAGE * 2)

template<int CAUSAL>
__global__ __launch_bounds__(128)
void attn_tc(const __nv_bfloat16* __restrict__ Qb, const __nv_bfloat16* __restrict__ Kb,
             const __nv_bfloat16* __restrict__ Vb, __nv_bfloat16* __restrict__ O2,
             int Sk, int qstride, int qlooff, int kvstride, int kvlooff)
{
    extern __shared__ __nv_bfloat16 smb[];
    const uint32_t uS0 = smem_u32_of(smb);
    const uint32_t uS1 = uS0 + ASTAGE * 2;

    const int h = blockIdx.y;
    const int bx = CAUSAL ? ((int)gridDim.x - 1 - (int)blockIdx.x) : (int)blockIdx.x;
    const int r0 = bx * 64;
    const int tid = threadIdx.x, w = tid >> 5, lane = tid & 31;
    const int fr = lane & 15, fo = (lane >> 4) * 8;
    const int headoff = h * 64;

    #pragma unroll
    for (int i = 0; i < 8; i++) {
        int cid = i * 128 + tid;
        int plane = cid >> 9, row = (cid >> 3) & 63, seg = cid & 7;
        uint32_t dst = uS1 + (uint32_t)(plane * APLANE + row * APIT + seg * 8) * 2;
        const __nv_bfloat16* src = Qb + (size_t)(r0 + row) * qstride + plane * qlooff + headoff + seg * 8;
        CP_ASYNC16(dst, src);
    }
    CP_COMMIT();
    #pragma unroll
    for (int i = 0; i < 16; i++) {
        int cid = i * 128 + tid;
        int plane = cid >> 9, row = (cid >> 3) & 63, seg = cid & 7;
        uint32_t dst = uS0 + (uint32_t)(plane * APLANE + row * APIT + seg * 8) * 2;
        const __nv_bfloat16* base = (plane < 2) ? Kb : Vb;
        const __nv_bfloat16* src = base + (size_t)row * kvstride + (plane & 1) * kvlooff + headoff + seg * 8;
        CP_ASYNC16(dst, src);
    }
    CP_COMMIT();

    CP_WAIT(1);
    __syncthreads();
    uint32_t qh[4][4], ql[4][4];
    #pragma unroll
    for (int kt = 0; kt < 4; kt++) {
        uint32_t off = (uint32_t)(w * 16 + fr) * (APIT * 2) + (kt * 16 + fo) * 2;
        ldm_x4(qh[kt][0], qh[kt][1], qh[kt][2], qh[kt][3], uS0 + ASTAGE * 2 + off);
        ldm_x4(ql[kt][0], ql[kt][1], ql[kt][2], ql[kt][3], uS0 + ASTAGE * 2 + APLANE * 2 + off);
    }
    __syncthreads();

    float o[8][4];
    #pragma unroll
    for (int n = 0; n < 8; n++)
        #pragma unroll
        for (int q = 0; q < 4; q++) o[n][q] = 0.f;
    float m0 = -1e30f, m1 = -1e30f, l0 = 0.f, l1 = 0.f;

    const int nt = CAUSAL ? (bx + 1) : (Sk >> 6);
    for (int t = 0; t < nt; t++) {
        if (t + 1 < nt) {
            const int c1 = (t + 1) * 64;
            const uint32_t uSn = ((t + 1) & 1) ? uS1 : uS0;
            #pragma unroll
            for (int i = 0; i < 16; i++) {
                int cid = i * 128 + tid;
                int plane = cid >> 9, row = (cid >> 3) & 63, seg = cid & 7;
                uint32_t dst = uSn + (uint32_t)(plane * APLANE + row * APIT + seg * 8) * 2;
                const __nv_bfloat16* base = (plane < 2) ? Kb : Vb;
                const __nv_bfloat16* src = base + (size_t)(c1 + row) * kvstride + (plane & 1) * kvlooff + headoff + seg * 8;
                CP_ASYNC16(dst, src);
            }
        }
        CP_COMMIT();
        CP_WAIT(1);
        __syncthreads();

        const uint32_t uKhi = ((t & 1) ? uS1 : uS0);
        const uint32_t uKlo = uKhi + APLANE * 2;
        const uint32_t uVhi = uKhi + 2 * APLANE * 2;
        const uint32_t uVlo = uKhi + 3 * APLANE * 2;
        const int c0 = t * 64;

        float s[8][4];
        #pragma unroll
        for (int n = 0; n < 8; n++)
            #pragma unroll
            for (int q = 0; q < 4; q++) s[n][q] = 0.f;
        #pragma unroll
        for (int np = 0; np < 4; np++) {
            uint32_t bh[4][4], bl[4][4];
            #pragma unroll
            for (int kt = 0; kt < 4; kt++) {
                uint32_t off = (uint32_t)(np * 16 + fr) * (APIT * 2) + (kt * 16 + fo) * 2;
                ldm_x4(bh[kt][0], bh[kt][1], bh[kt][2], bh[kt][3], uKhi + off);
                ldm_x4(bl[kt][0], bl[kt][1], bl[kt][2], bl[kt][3], uKlo + off);
            }
            #pragma unroll
            for (int kt = 0; kt < 4; kt++) {
                mma16816(s[np*2+0], qh[kt], bh[kt][0], bh[kt][2]);
                mma16816(s[np*2+1], qh[kt], bh[kt][1], bh[kt][3]);
                mma16816(s[np*2+0], ql[kt], bh[kt][0], bh[kt][2]);
                mma16816(s[np*2+1], ql[kt], bh[kt][1], bh[kt][3]);
                mma16816(s[np*2+0], qh[kt], bl[kt][0], bl[kt][2]);
                mma16816(s[np*2+1], qh[kt], bl[kt][1], bl[kt][3]);
            }
        }
        #pragma unroll
        for (int n = 0; n < 8; n++) {
            s[n][0] *= 0.125f; s[n][1] *= 0.125f;
            s[n][2] *= 0.125f; s[n][3] *= 0.125f;
        }

        if (CAUSAL && t == nt - 1) {
            int gr0 = r0 + w * 16 + (lane >> 2);
            int gr1 = gr0 + 8;
            #pragma unroll
            for (int n = 0; n < 8; n++) {
                int col = c0 + n * 8 + (lane & 3) * 2;
                if (col     > gr0) s[n][0] = -1e30f;
                if (col + 1 > gr0) s[n][1] = -1e30f;
                if (col     > gr1) s[n][2] = -1e30f;
                if (col + 1 > gr1) s[n][3] = -1e30f;
            }
        }

        float mx0 = -1e30f, mx1 = -1e30f;
        #pragma unroll
        for (int n = 0; n < 8; n++) {
            mx0 = fmaxf(mx0, fmaxf(s[n][0], s[n][1]));
            mx1 = fmaxf(mx1, fmaxf(s[n][2], s[n][3]));
        }
        mx0 = fmaxf(mx0, __shfl_xor_sync(0xffffffffu, mx0, 1));
        mx0 = fmaxf(mx0, __shfl_xor_sync(0xffffffffu, mx0, 2));
        mx1 = fmaxf(mx1, __shfl_xor_sync(0xffffffffu, mx1, 1));
        mx1 = fmaxf(mx1, __shfl_xor_sync(0xffffffffu, mx1, 2));
        float mn0 = fmaxf(m0, mx0), mn1 = fmaxf(m1, mx1);
        float cor0 = __expf(m0 - mn0), cor1 = __expf(m1 - mn1);
        m0 = mn0; m1 = mn1;
        float ps0 = 0.f, ps1 = 0.f;
        #pragma unroll
        for (int n = 0; n < 8; n++) {
            s[n][0] = __expf(s[n][0] - mn0);
            s[n][1] = __expf(s[n][1] - mn0);
            s[n][2] = __expf(s[n][2] - mn1);
            s[n][3] = __expf(s[n][3] - mn1);
            ps0 += s[n][0] + s[n][1];
            ps1 += s[n][2] + s[n][3];
        }
        ps0 += __shfl_xor_sync(0xffffffffu, ps0, 1);
        ps0 += __shfl_xor_sync(0xffffffffu, ps0, 2);
        ps1 += __shfl_xor_sync(0xffffffffu, ps1, 1);
        ps1 += __shfl_xor_sync(0xffffffffu, ps1, 2);
        l0 = l0 * cor0 + ps0;
        l1 = l1 * cor1 + ps1;
        #pragma unroll
        for (int n = 0; n < 8; n++) {
            o[n][0] *= cor0; o[n][1] *= cor0;
            o[n][2] *= cor1; o[n][3] *= cor1;
        }

        uint32_t ph[4][4], pl[4][4];
        #pragma unroll
        for (int kt = 0; kt < 4; kt++) {
            int n0 = 2 * kt, n1 = n0 + 1;
            pack_hl(s[n0][0], s[n0][1], ph[kt][0], pl[kt][0]);
            pack_hl(s[n0][2], s[n0][3], ph[kt][1], pl[kt][1]);
            pack_hl(s[n1][0], s[n1][1], ph[kt][2], pl[kt][2]);
            pack_hl(s[n1][2], s[n1][3], ph[kt][3], pl[kt][3]);
        }

        #pragma unroll
        for (int dp = 0; dp < 4; dp++) {
            uint32_t vh[4][4], vl[4][4];
            #pragma unroll
            for (int kj = 0; kj < 4; kj++) {
                uint32_t off = (uint32_t)(kj * 16 + fr) * (APIT * 2) + (dp * 16 + fo) * 2;
                ldm_x4t(vh[kj][0], vh[kj][1], vh[kj][2], vh[kj][3], uVhi + off);
                ldm_x4t(vl[kj][0], vl[kj][1], vl[kj][2], vl[kj][3], uVlo + off);
            }
            #pragma unroll
            for (int kj = 0; kj < 4; kj++) {
                mma16816(o[dp*2+0], ph[kj], vh[kj][0], vh[kj][1]);
                mma16816(o[dp*2+1], ph[kj], vh[kj][2], vh[kj][3]);
                mma16816(o[dp*2+0], pl[kj], vh[kj][0], vh[kj][1]);
                mma16816(o[dp*2+1], pl[kj], vh[kj][2], vh[kj][3]);
                mma16816(o[dp*2+0], ph[kj], vl[kj][0], vl[kj][1]);
                mma16816(o[dp*2+1], ph[kj], vl[kj][2], vl[kj][3]);
            }
        }
        __syncthreads();
    }

    // epilogue -> i2 layout (ext row stride 2048 for N=1024)
    float inv0 = 1.f / l0, inv1 = 1.f / l1;
    int gr0 = r0 + w * 16 + (lane >> 2);
    unsigned short* D = (unsigned short*)O2;
    #pragma unroll
    for (int n = 0; n < 8; n++) {
        int col = headoff + n * 8 + (lane & 3) * 2;
        uint32_t coff = ((uint32_t)(col >> 5) << 6) + (col & 31);
        float v0 = o[n][0] * inv0, v1 = o[n][1] * inv0;
        float v2 = o[n][2] * inv1, v3 = o[n][3] * inv1;
        unsigned short h0,h1,h2,h3,l0s,l1s,l2s,l3s;
        split1(v0, h0, l0s); split1(v1, h1, l1s);
        split1(v2, h2, l2s); split1(v3, h3, l3s);
        size_t b0r = (size_t)gr0 * 2048 + coff;
        size_t b1r = (size_t)(gr0 + 8) * 2048 + coff;
        *(ushort2*)(D + b0r)      = make_ushort2(h0, h1);
        *(ushort2*)(D + b0r + 32) = make_ushort2(l0s, l1s);
        *(ushort2*)(D + b1r)      = make_ushort2(h2, h3);
        *(ushort2*)(D + b1r + 32) = make_ushort2(l2s, l3s);
    }
}

// ===================== launch =====================
extern "C" void kernel_launch(void* const* d_in, const int* in_sizes, int n_in,
                              void* d_out, int out_size)
{
    const float* wemb = (const float*)d_in[0];
    const float* pemb = (const float*)d_in[1];
    const float* Wq_m = (const float*)d_in[2];
    const float* bq_m = (const float*)d_in[3];
    const float* Wk_m = (const float*)d_in[4];
    const float* bk_m = (const float*)d_in[5];
    const float* Wv_m = (const float*)d_in[6];
    const float* bv_m = (const float*)d_in[7];
    const float* Wq_c = (const float*)d_in[8];
    const float* bq_c = (const float*)d_in[9];
    const float* Wk_c = (const float*)d_in[10];
    const float* bk_c = (const float*)d_in[11];
    const float* Wv_c = (const float*)d_in[12];
    const float* bv_c = (const float*)d_in[13];
    const float* W1   = (const float*)d_in[14];
    const float* b1   = (const float*)d_in[15];
    const float* W2   = (const float*)d_in[16];
    const float* b2   = (const float*)d_in[17];
    float* out = (float*)d_out;

    __nv_bfloat16 *QKV2m, *KV2c, *Q2c;
    __nv_bfloat16 *wemb2, *pemb2, *word2, *cross2;
    __nv_bfloat16 *Wqkvm2, *Wqc2, *Wkvc2, *W12, *W22, *Hf2;
    cudaGetSymbolAddress((void**)&QKV2m, g_QKV2m);
    cudaGetSymbolAddress((void**)&KV2c, g_KV2c);
    cudaGetSymbolAddress((void**)&Q2c, g_Q2c);
    cudaGetSymbolAddress((void**)&wemb2, g_wemb2);
    cudaGetSymbolAddress((void**)&pemb2, g_pemb2);
    cudaGetSymbolAddress((void**)&word2, g_word2);
    cudaGetSymbolAddress((void**)&cross2, g_cross2);
    cudaGetSymbolAddress((void**)&Wqkvm2, g_Wqkvm2);
    cudaGetSymbolAddress((void**)&Wqc2, g_Wqc2);
    cudaGetSymbolAddress((void**)&Wkvc2, g_Wkvc2);
    cudaGetSymbolAddress((void**)&W12, g_W12);
    cudaGetSymbolAddress((void**)&W22, g_W22);
    cudaGetSymbolAddress((void**)&Hf2, g_Hf2);

    cudaFuncSetAttribute((const void*)gemm_tc<0>,
                         cudaFuncAttributeMaxDynamicSharedMemorySize, GEMM_SMEM);
    cudaFuncSetAttribute((const void*)gemm_tc<1>,
                         cudaFuncAttributeMaxDynamicSharedMemorySize, GEMM_SMEM);
    cudaFuncSetAttribute((const void*)gemm_tc<2>,
                         cudaFuncAttributeMaxDynamicSharedMemorySize, GEMM_SMEM);
    cudaFuncSetAttribute((const void*)attn_tc<0>,
                         cudaFuncAttributeMaxDynamicSharedMemorySize, ATTN_SMEM);
    cudaFuncSetAttribute((const void*)attn_tc<1>,
                         cudaFuncAttributeMaxDynamicSharedMemorySize, ATTN_SMEM);

    // ---- single batched split launch (i2 outputs; weights concatenated) ----
    SplitJobs J;
    const float* srcs[10]  = {wemb, pemb, Wq_m, Wk_m, Wv_m, Wq_c, Wk_c, Wv_c, W1, W2};
    __nv_bfloat16* dsts[10] = {wemb2, pemb2,
                               Wqkvm2, Wqkvm2 + (size_t)1024*2048, Wqkvm2 + (size_t)2048*2048,
                               Wqc2,
                               Wkvc2, Wkvc2 + (size_t)1024*2048,
                               W12, W22};
    int Ms[10]   = {2048, 1024, 1024, 1024, 1024, 1024, 1024, 1024, 4096, 1024};
    int Ks[10]   = {1024, 1024, 1024, 1024, 1024, 1024, 1024, 1024, 1024, 4096};
    int cum = 0;
    for (int j = 0; j < 10; j++) {
        J.src[j] = srcs[j]; J.dst[j] = dsts[j];
        J.K[j] = Ks[j];
        J.cum[j] = cum;
        cum += Ms[j] * (Ks[j] >> 2);
    }
    J.cum[10] = cum;
    split_all<<<(cum + 255) / 256, 256>>>(J);                                            // 1

    Bias4 Bqkv  = {{bq_m, bk_m, bv_m, bq_m}};
    Bias4 Bkvc  = {{bk_c, bv_c, bk_c, bv_c}};
    Bias4 Bqc   = {{bq_c, bq_c, bq_c, bq_c}};
    Bias4 Bf1   = {{b1, b1 + 1024, b1 + 2048, b1 + 3072}};
    Bias4 Bf2   = {{b2, b2, b2, b2}};

    // fused QKV(self): planar out, stride 6144
    gemm_tc<2><<<dim3(24, 16), 512, GEMM_SMEM>>>(wemb2, Wqkvm2, Bqkv, nullptr, QKV2m, 2048, 3072, 1024); // 2
    // fused KV(cross): planar out, stride 4096
    gemm_tc<2><<<dim3(16, 8),  512, GEMM_SMEM>>>(pemb2, Wkvc2, Bkvc, nullptr, KV2c, 1024, 2048, 1024);   // 3
    // causal self-attention -> word2 (i2)
    attn_tc<1><<<dim3(32, 16), 128, ATTN_SMEM>>>(QKV2m, QKV2m + 1024, QKV2m + 2048, word2,
                                                 2048, 6144, 3072, 6144, 3072);                          // 4
    // cross Q projection -> Q2c (planar)
    gemm_tc<2><<<dim3(8, 16), 512, GEMM_SMEM>>>(word2, Wqc2, Bqc, nullptr, Q2c, 2048, 1024, 1024);       // 5
    // cross attention -> cross2 (i2)
    attn_tc<0><<<dim3(32, 16), 128, ATTN_SMEM>>>(Q2c, KV2c, KV2c + 1024, cross2,
                                                 1024, 2048, 1024, 4096, 2048);                          // 6
    // FFN1 -> Hf2 (i2, relu)
    gemm_tc<1><<<dim3(32, 16), 512, GEMM_SMEM>>>(cross2, W12, Bf1, nullptr, Hf2, 2048, 4096, 1024);      // 7
    // FFN2 -> out (fp32)
    gemm_tc<0><<<dim3(8, 16), 512, GEMM_SMEM>>>(Hf2, W22, Bf2, out, nullptr, 2048, 1024, 4096);          // 8
}